// round 11
// baseline (speedup 1.0000x reference)
#include <cuda_runtime.h>
#include <cuda_fp16.h>
#include <cstdint>
#include <cstddef>

// Problem constants (fixed by the dataset)
#define NR    16384
#define NCH   65536
#define NP    16384
#define DIM   64
#define ERC   65536
#define EPASS 65536
#define VT    64     // channel rows per fused-kernel block

// Device scratch (allocation-free rule: __device__ globals)
__device__ float  g_s   [(size_t)NCH * DIM];  // 16 MB: sum of h_packet per channel
__device__ float  g_cnt [NCH];                // edge count per channel
__device__ float  g_hin [(size_t)NCH * DIM];  // 16 MB
__device__ float  g_hout[(size_t)NCH * DIM];  // 16 MB
__device__ float  g_min [(size_t)NCH * 32];   // 8 MB (dense write, no zero needed)
__device__ float  g_mout[(size_t)NCH * 32];   // 8 MB
__device__ uint4  g_wfrag[32 * 4 * 4 * 32];   // 256 KB: W_p as MMA B-fragments
__device__ float  g_bperm[2048];              // b_p permuted: bperm[k*64+d] = b_p[d*32+k]

// Side stream + fork/join events, created once at load time.
struct SideStream {
    cudaStream_t s2;
    cudaEvent_t evFork, evJoin;
    SideStream() {
        cudaStreamCreate(&s2);
        cudaEventCreateWithFlags(&evFork, cudaEventDisableTiming);
        cudaEventCreateWithFlags(&evJoin, cudaEventDisableTiming);
    }
};
static SideStream g_ss;

__device__ __forceinline__ void red_add_v4(float* p, float4 v) {
    asm volatile("red.global.add.v4.f32 [%0], {%1,%2,%3,%4};"
                 :: "l"(p), "f"(v.x), "f"(v.y), "f"(v.z), "f"(v.w) : "memory");
}
__device__ __forceinline__ void red_add_f(float* p, float v) {
    asm volatile("red.global.add.f32 [%0], %1;" :: "l"(p), "f"(v) : "memory");
}
__device__ __forceinline__ uint32_t smem_u32(const void* p) {
    return (uint32_t)__cvta_generic_to_shared(p);
}
__device__ __forceinline__ uint4 f8_to_h8(float4 lo, float4 hi) {
    __half2 h0 = __floats2half2_rn(lo.x, lo.y);
    __half2 h1 = __floats2half2_rn(lo.z, lo.w);
    __half2 h2 = __floats2half2_rn(hi.x, hi.y);
    __half2 h3 = __floats2half2_rn(hi.z, hi.w);
    return make_uint4(*(unsigned*)&h0, *(unsigned*)&h1,
                      *(unsigned*)&h2, *(unsigned*)&h3);
}

// ---------------------------------------------------------------------------
// K0a (main): zero hin/hout/s/cnt
__global__ void zero_hs_kernel(float4* __restrict__ hin, float4* __restrict__ hout,
                               float4* __restrict__ s, float4* __restrict__ cnt) {
    const int n_h = (NCH * DIM) / 4;
    const int n_c = NCH / 4;
    float4 z = make_float4(0.f, 0.f, 0.f, 0.f);
    int stride = gridDim.x * blockDim.x;
    for (int i = blockIdx.x * blockDim.x + threadIdx.x; i < n_h; i += stride) {
        hin[i] = z; hout[i] = z; s[i] = z;
    }
    for (int i = blockIdx.x * blockDim.x + threadIdx.x; i < n_c; i += stride) cnt[i] = z;
}
// K0b (side): zero out
__global__ void zero_out_kernel(float4* __restrict__ out) {
    int i = blockIdx.x * blockDim.x + threadIdx.x;
    out[i] = make_float4(0.f, 0.f, 0.f, 0.f);
}

// ---------------------------------------------------------------------------
// K1: all three scatters in one launch:
//   list0: hin[output_dst] += h_router[output_src]
//   list1: hout[input_inv_dst] += h_router[input_inv_src]
//   list2: s[pass_dst] += h_packet[pass_src]; cnt[pass_dst] += 1
__global__ void mega_scatter_kernel(
        const int* __restrict__ src0, const int* __restrict__ dst0,
        const int* __restrict__ src1, const int* __restrict__ dst1,
        const int* __restrict__ src2, const int* __restrict__ dst2,
        const float* __restrict__ h_router, const float* __restrict__ h_packet,
        float* __restrict__ hin, float* __restrict__ hout,
        float* __restrict__ s, float* __restrict__ cnt) {
    int tid = blockIdx.x * blockDim.x + threadIdx.x;
    int e = tid >> 4;
    int c = tid & 15;
    const int* src; const int* dst; const float* h; float* acc;
    bool do_cnt = false;
    if (e < ERC)          { src = src0; dst = dst0; h = h_router; acc = hin; }
    else if (e < 2 * ERC) { e -= ERC; src = src1; dst = dst1; h = h_router; acc = hout; }
    else if (e < 3 * ERC) { e -= 2 * ERC; src = src2; dst = dst2; h = h_packet; acc = s;
                            do_cnt = (c == 0); }
    else return;
    int sidx = src[e];
    int d = dst[e];
    float4 v = *(const float4*)(h + (size_t)sidx * DIM + c * 4);
    red_add_v4(acc + (size_t)d * DIM + c * 4, v);
    if (do_cnt) red_add_f(cnt + d, 1.0f);
}

// ---------------------------------------------------------------------------
// K2a (side): extract W_p into MMA B-fragment order. Each warp handles one k:
// loads W^(k) (row d = W_p[d*32+k], fp16, swizzled) into its own smem slice,
// then runs the exact consumer ldmatrix pattern and stores the fragments.
// Layout: g_wfrag[((k*4 + ks)*4 + nb)*32 + lane] = {bf0,bf1,bf2,bf3}.
__global__ void __launch_bounds__(128) prep_w_frag(
        const float* __restrict__ Wp, uint4* __restrict__ wfrag) {
    __shared__ __align__(16) __half Wsm[4][64 * 64];   // 32 KB
    const int t = threadIdx.x, wid = t >> 5, lane = t & 31;
    const int k = blockIdx.x * 4 + wid;
    __half* W = Wsm[wid];
#pragma unroll
    for (int i = 0; i < 16; i++) {
        int idx = i * 32 + lane;         // 0..511
        int d = idx >> 3, ch = idx & 7;
        const float4* gp = (const float4*)(Wp + (size_t)(d * 32 + k) * DIM + ch * 8);
        *(uint4*)(W + (d << 6) + ((ch ^ (d & 7)) << 3)) = f8_to_h8(gp[0], gp[1]);
    }
    __syncwarp();
#pragma unroll
    for (int ks = 0; ks < 4; ks++) {
        const int lrow = lane & 15;
        const int lch  = 2 * ks + (lane >> 4);
#pragma unroll
        for (int nb = 0; nb < 4; nb++) {
            int r = nb * 16 + lrow;
            uint32_t addr = smem_u32(W + r * 64 + (lch ^ (r & 7)) * 8);
            uint32_t b0, b1, b2, b3;
            asm volatile("ldmatrix.sync.aligned.m8n8.x4.shared.b16 {%0,%1,%2,%3}, [%4];"
                : "=r"(b0), "=r"(b1), "=r"(b2), "=r"(b3) : "r"(addr));
            wfrag[((k * 4 + ks) * 4 + nb) * 32 + lane] = make_uint4(b0, b1, b2, b3);
        }
    }
}
// K2b (side): permute b_p
__global__ void prep_bias(const float* __restrict__ bp, float* __restrict__ bperm) {
    int i = blockIdx.x * blockDim.x + threadIdx.x;   // 2048 threads
    int k = i >> 6, d = i & 63;
    bperm[i] = bp[d * 32 + k];
}

// ---------------------------------------------------------------------------
// K3: fused bilinear. Per 64-channel tile (128 threads, 4 warps, 16 rows/warp):
//   for k: P[v,d] = sum_j S[v,j]*W[(d,k),j] + cnt[v]*b_p[(d,k)]  (mma.m16n8k16)
//          m_in[v,k] = sum_d hin[v,d]*P[v,d]; m_out with hout.
// No barriers in the k loop: W comes pre-fragmented via coalesced LDG, h is
// hoisted into registers, A fragments are k-invariant.
__global__ void __launch_bounds__(128) fused_bilinear(
        const float* __restrict__ s, const float* __restrict__ cnt,
        const float* __restrict__ hin, const float* __restrict__ hout,
        const uint4* __restrict__ wfrag, const float* __restrict__ bperm,
        float* __restrict__ min_, float* __restrict__ mout_) {
    __shared__ __align__(16) __half Ssm[64 * 64];   // swizzled
    __shared__ float Min[64 * 33], Mout[64 * 33];
    __shared__ float BPs[2048];
    __shared__ float CNTs[64];

    const int t = threadIdx.x, wid = t >> 5, lane = t & 31;
    const int vt0 = blockIdx.x * VT;

#pragma unroll
    for (int i = 0; i < 4; i++) {
        int idx = i * 128 + t;           // 0..511
        int r = idx >> 3, ch = idx & 7;
        const float4* gp = (const float4*)(s + (size_t)(vt0 + r) * DIM + ch * 8);
        *(uint4*)(Ssm + r * 64 + ((ch ^ (r & 7)) << 3)) = f8_to_h8(gp[0], gp[1]);
    }
    for (int i = t; i < 512; i += 128)
        ((float4*)BPs)[i] = ((const float4*)bperm)[i];
    if (t < 64) CNTs[t] = cnt[vt0 + t];
    __syncthreads();

    const int vbase = wid * 16;
    uint32_t a[4][4];
    {
        const int r = vbase + (lane & 15);
#pragma unroll
        for (int ks = 0; ks < 4; ks++) {
            int lch = 2 * ks + (lane >> 4);
            uint32_t addr = smem_u32(Ssm + r * 64 + ((lch ^ (r & 7)) << 3));
            asm volatile("ldmatrix.sync.aligned.m8n8.x4.shared.b16 {%0,%1,%2,%3}, [%4];"
                : "=r"(a[ks][0]), "=r"(a[ks][1]), "=r"(a[ks][2]), "=r"(a[ks][3])
                : "r"(addr));
        }
    }
    const int tr0 = vbase + (lane >> 2);   // local row
    const int tr1 = tr0 + 8;
    const float cnt0 = CNTs[tr0];
    const float cnt1 = CNTs[tr1];
    const int dq = 2 * (lane & 3);

    // hoist h into registers (k-invariant)
    float2 hi0[8], hi1[8], ho0[8], ho1[8];
#pragma unroll
    for (int n8 = 0; n8 < 8; n8++) {
        int d0 = n8 * 8 + dq;
        hi0[n8] = *(const float2*)(hin  + (size_t)(vt0 + tr0) * DIM + d0);
        hi1[n8] = *(const float2*)(hin  + (size_t)(vt0 + tr1) * DIM + d0);
        ho0[n8] = *(const float2*)(hout + (size_t)(vt0 + tr0) * DIM + d0);
        ho1[n8] = *(const float2*)(hout + (size_t)(vt0 + tr1) * DIM + d0);
    }

    for (int k = 0; k < 32; k++) {
        float pacc[8][4];
#pragma unroll
        for (int n8 = 0; n8 < 8; n8++)
#pragma unroll
            for (int j = 0; j < 4; j++) pacc[n8][j] = 0.f;

        const uint4* wf = wfrag + k * 512 + lane;
#pragma unroll
        for (int ks = 0; ks < 4; ks++) {
            uint4 bf[4];
#pragma unroll
            for (int nb = 0; nb < 4; nb++) bf[nb] = wf[(ks * 4 + nb) * 32];
#pragma unroll
            for (int n8 = 0; n8 < 8; n8++) {
                uint32_t b0 = (n8 & 1) ? bf[n8 >> 1].y : bf[n8 >> 1].x;
                uint32_t b1 = (n8 & 1) ? bf[n8 >> 1].w : bf[n8 >> 1].z;
                asm volatile(
                    "mma.sync.aligned.m16n8k16.row.col.f32.f16.f16.f32 "
                    "{%0,%1,%2,%3}, {%4,%5,%6,%7}, {%8,%9}, {%0,%1,%2,%3};"
                    : "+f"(pacc[n8][0]), "+f"(pacc[n8][1]),
                      "+f"(pacc[n8][2]), "+f"(pacc[n8][3])
                    : "r"(a[ks][0]), "r"(a[ks][1]), "r"(a[ks][2]), "r"(a[ks][3]),
                      "r"(b0), "r"(b1));
            }
        }

        float pin0 = 0.f, pin1 = 0.f, po0 = 0.f, po1 = 0.f;
        const float* bpk = BPs + k * 64;
#pragma unroll
        for (int n8 = 0; n8 < 8; n8++) {
            float2 bp2 = *(const float2*)(bpk + n8 * 8 + dq);
            float p00 = pacc[n8][0] + cnt0 * bp2.x;
            float p01 = pacc[n8][1] + cnt0 * bp2.y;
            float p10 = pacc[n8][2] + cnt1 * bp2.x;
            float p11 = pacc[n8][3] + cnt1 * bp2.y;
            pin0 += p00 * hi0[n8].x + p01 * hi0[n8].y;
            pin1 += p10 * hi1[n8].x + p11 * hi1[n8].y;
            po0  += p00 * ho0[n8].x + p01 * ho0[n8].y;
            po1  += p10 * ho1[n8].x + p11 * ho1[n8].y;
        }
        pin0 += __shfl_xor_sync(0xffffffffu, pin0, 1);
        pin0 += __shfl_xor_sync(0xffffffffu, pin0, 2);
        pin1 += __shfl_xor_sync(0xffffffffu, pin1, 1);
        pin1 += __shfl_xor_sync(0xffffffffu, pin1, 2);
        po0  += __shfl_xor_sync(0xffffffffu, po0, 1);
        po0  += __shfl_xor_sync(0xffffffffu, po0, 2);
        po1  += __shfl_xor_sync(0xffffffffu, po1, 1);
        po1  += __shfl_xor_sync(0xffffffffu, po1, 2);
        if ((lane & 3) == 0) {
            Min [tr0 * 33 + k] = pin0;
            Min [tr1 * 33 + k] = pin1;
            Mout[tr0 * 33 + k] = po0;
            Mout[tr1 * 33 + k] = po1;
        }
    }
    __syncthreads();

    // dense writeback
    for (int i = t; i < 512; i += 128) {
        int r = i >> 3, c = (i & 7) * 4;
        float4 vi = make_float4(Min[r * 33 + c], Min[r * 33 + c + 1],
                                Min[r * 33 + c + 2], Min[r * 33 + c + 3]);
        float4 vo = make_float4(Mout[r * 33 + c], Mout[r * 33 + c + 1],
                                Mout[r * 33 + c + 2], Mout[r * 33 + c + 3]);
        *(float4*)(min_  + (size_t)(vt0 + r) * 32 + c) = vi;
        *(float4*)(mout_ + (size_t)(vt0 + r) * 32 + c) = vo;
    }
}

// ---------------------------------------------------------------------------
// K4: gather channel -> router into d_out. 8 lanes per edge, float4 chunks.
__global__ void gather_kernel(const int* __restrict__ isrc, const int* __restrict__ idst,
                              const int* __restrict__ oisrc, const int* __restrict__ oidst,
                              const float* __restrict__ min_, const float* __restrict__ mout_,
                              float* __restrict__ out) {
    int gtid = blockIdx.x * blockDim.x + threadIdx.x;
    int e = gtid >> 3;
    int c = gtid & 7;
    if (e < ERC) {
        int s = isrc[e], d = idst[e];
        float4 v = *(const float4*)(min_ + (size_t)s * 32 + c * 4);
        red_add_v4(out + (size_t)d * DIM + c * 4, v);
    } else if (e < 2 * ERC) {
        int ee = e - ERC;
        int s = oisrc[ee], d = oidst[ee];
        float4 v = *(const float4*)(mout_ + (size_t)s * 32 + c * 4);
        red_add_v4(out + (size_t)d * DIM + 32 + c * 4, v);
    }
}

// ---------------------------------------------------------------------------
// K5: relu epilogue on out
__global__ void relu_kernel(float4* __restrict__ out) {
    int i = blockIdx.x * blockDim.x + threadIdx.x;
    float4 v = out[i];
    v.x = fmaxf(v.x, 0.f); v.y = fmaxf(v.y, 0.f);
    v.z = fmaxf(v.z, 0.f); v.w = fmaxf(v.w, 0.f);
    out[i] = v;
}

// ===========================================================================
extern "C" void kernel_launch(void* const* d_in, const int* in_sizes, int n_in,
                              void* d_out, int out_size) {
    const float* h_router       = (const float*)d_in[0];
    const float* h_packet       = (const float*)d_in[1];
    const float* W_p            = (const float*)d_in[2];
    const float* b_p            = (const float*)d_in[3];
    // d_in[4] = W_c, d_in[5] = b_c : dead code in reference
    const int* output_src       = (const int*)d_in[6];
    const int* output_dst       = (const int*)d_in[7];
    const int* input_inv_src    = (const int*)d_in[8];
    const int* input_inv_dst    = (const int*)d_in[9];
    const int* pass_src         = (const int*)d_in[10];
    const int* pass_dst         = (const int*)d_in[11];
    const int* input_src        = (const int*)d_in[12];
    const int* input_dst        = (const int*)d_in[13];
    const int* output_inv_src   = (const int*)d_in[14];
    const int* output_inv_dst   = (const int*)d_in[15];
    float* out = (float*)d_out;

    float *p_s, *p_cnt, *p_hin, *p_hout, *p_min, *p_mout, *p_bperm;
    uint4* p_wfrag;
    cudaGetSymbolAddress((void**)&p_s,     g_s);
    cudaGetSymbolAddress((void**)&p_cnt,   g_cnt);
    cudaGetSymbolAddress((void**)&p_hin,   g_hin);
    cudaGetSymbolAddress((void**)&p_hout,  g_hout);
    cudaGetSymbolAddress((void**)&p_min,   g_min);
    cudaGetSymbolAddress((void**)&p_mout,  g_mout);
    cudaGetSymbolAddress((void**)&p_wfrag, g_wfrag);
    cudaGetSymbolAddress((void**)&p_bperm, g_bperm);

    // Fork: side stream preps W fragments + bias permutation, zeroes out.
    cudaEventRecord(g_ss.evFork, 0);
    cudaStreamWaitEvent(g_ss.s2, g_ss.evFork, 0);
    prep_w_frag<<<8, 128, 0, g_ss.s2>>>(W_p, p_wfrag);
    prep_bias<<<8, 256, 0, g_ss.s2>>>(b_p, p_bperm);
    zero_out_kernel<<<(NR * DIM) / (4 * 256), 256, 0, g_ss.s2>>>((float4*)out);
    cudaEventRecord(g_ss.evJoin, g_ss.s2);

    // Main: zero accumulators, then all three scatters in one launch
    zero_hs_kernel<<<4096, 256>>>((float4*)p_hin, (float4*)p_hout,
                                  (float4*)p_s, (float4*)p_cnt);
    mega_scatter_kernel<<<(3 * ERC * 16) / 256, 256>>>(
        output_src, output_dst, input_inv_src, input_inv_dst,
        pass_src, pass_dst, h_router, h_packet,
        p_hin, p_hout, p_s, p_cnt);

    // Join, then fused bilinear (needs scatters + prep)
    cudaStreamWaitEvent(0, g_ss.evJoin, 0);
    fused_bilinear<<<NCH / VT, 128>>>(p_s, p_cnt, p_hin, p_hout,
                                      p_wfrag, p_bperm, p_min, p_mout);

    // channel -> router gathers into out
    gather_kernel<<<(2 * ERC * 8) / 256, 256>>>(input_src, input_dst,
                                                output_inv_src, output_inv_dst,
                                                p_min, p_mout, out);

    // relu epilogue
    relu_kernel<<<(NR * DIM) / (4 * 256), 256>>>((float4*)out);
}

// round 12
// speedup vs baseline: 1.2431x; 1.2431x over previous
#include <cuda_runtime.h>
#include <cuda_fp16.h>
#include <cstdint>
#include <cstddef>

// Problem constants (fixed by the dataset)
#define NR    16384
#define NCH   65536
#define NP    16384
#define DIM   64
#define ERC   65536
#define EPASS 65536
#define VT    64     // channel rows per fused-kernel block

// Device scratch (allocation-free rule: __device__ globals)
__device__ float  g_s   [(size_t)NCH * DIM];  // 16 MB: sum of h_packet per channel
__device__ float  g_cnt [NCH];                // edge count per channel
__device__ float  g_hin [(size_t)NCH * DIM];  // 16 MB
__device__ float  g_hout[(size_t)NCH * DIM];  // 16 MB
__device__ float  g_min [(size_t)NCH * 32];   // 8 MB (dense write, no zero needed)
__device__ float  g_mout[(size_t)NCH * 32];   // 8 MB
__device__ uint4  g_wfrag[32 * 4 * 4 * 32];   // 256 KB: W_p as MMA B-fragments
__device__ float  g_bperm[2048];              // b_p permuted: bperm[k*64+d] = b_p[d*32+k]

// Side stream + fork/join events, created once at load time.
struct SideStream {
    cudaStream_t s2;
    cudaEvent_t evFork, evJoin;
    SideStream() {
        cudaStreamCreate(&s2);
        cudaEventCreateWithFlags(&evFork, cudaEventDisableTiming);
        cudaEventCreateWithFlags(&evJoin, cudaEventDisableTiming);
    }
};
static SideStream g_ss;

__device__ __forceinline__ void red_add_v4(float* p, float4 v) {
    asm volatile("red.global.add.v4.f32 [%0], {%1,%2,%3,%4};"
                 :: "l"(p), "f"(v.x), "f"(v.y), "f"(v.z), "f"(v.w) : "memory");
}
__device__ __forceinline__ void red_add_f(float* p, float v) {
    asm volatile("red.global.add.f32 [%0], %1;" :: "l"(p), "f"(v) : "memory");
}
__device__ __forceinline__ uint32_t smem_u32(const void* p) {
    return (uint32_t)__cvta_generic_to_shared(p);
}
__device__ __forceinline__ uint4 f8_to_h8(float4 lo, float4 hi) {
    __half2 h0 = __floats2half2_rn(lo.x, lo.y);
    __half2 h1 = __floats2half2_rn(lo.z, lo.w);
    __half2 h2 = __floats2half2_rn(hi.x, hi.y);
    __half2 h3 = __floats2half2_rn(hi.z, hi.w);
    return make_uint4(*(unsigned*)&h0, *(unsigned*)&h1,
                      *(unsigned*)&h2, *(unsigned*)&h3);
}

// ---------------------------------------------------------------------------
// K0a (main): zero hin/hout/s/cnt
__global__ void zero_hs_kernel(float4* __restrict__ hin, float4* __restrict__ hout,
                               float4* __restrict__ s, float4* __restrict__ cnt) {
    const int n_h = (NCH * DIM) / 4;
    const int n_c = NCH / 4;
    float4 z = make_float4(0.f, 0.f, 0.f, 0.f);
    int stride = gridDim.x * blockDim.x;
    for (int i = blockIdx.x * blockDim.x + threadIdx.x; i < n_h; i += stride) {
        hin[i] = z; hout[i] = z; s[i] = z;
    }
    for (int i = blockIdx.x * blockDim.x + threadIdx.x; i < n_c; i += stride) cnt[i] = z;
}
// K0b (side): zero out
__global__ void zero_out_kernel(float4* __restrict__ out) {
    int i = blockIdx.x * blockDim.x + threadIdx.x;
    out[i] = make_float4(0.f, 0.f, 0.f, 0.f);
}

// ---------------------------------------------------------------------------
// K1: all three scatters in one launch.
__global__ void mega_scatter_kernel(
        const int* __restrict__ src0, const int* __restrict__ dst0,
        const int* __restrict__ src1, const int* __restrict__ dst1,
        const int* __restrict__ src2, const int* __restrict__ dst2,
        const float* __restrict__ h_router, const float* __restrict__ h_packet,
        float* __restrict__ hin, float* __restrict__ hout,
        float* __restrict__ s, float* __restrict__ cnt) {
    int tid = blockIdx.x * blockDim.x + threadIdx.x;
    int e = tid >> 4;
    int c = tid & 15;
    const int* src; const int* dst; const float* h; float* acc;
    bool do_cnt = false;
    if (e < ERC)          { src = src0; dst = dst0; h = h_router; acc = hin; }
    else if (e < 2 * ERC) { e -= ERC; src = src1; dst = dst1; h = h_router; acc = hout; }
    else if (e < 3 * ERC) { e -= 2 * ERC; src = src2; dst = dst2; h = h_packet; acc = s;
                            do_cnt = (c == 0); }
    else return;
    int sidx = src[e];
    int d = dst[e];
    float4 v = *(const float4*)(h + (size_t)sidx * DIM + c * 4);
    red_add_v4(acc + (size_t)d * DIM + c * 4, v);
    if (do_cnt) red_add_f(cnt + d, 1.0f);
}

// ---------------------------------------------------------------------------
// K2a (side): extract W_p into MMA B-fragment order (one warp per k).
// Layout: g_wfrag[((k*4 + ks)*4 + nb)*32 + lane] = {bf0,bf1,bf2,bf3}.
__global__ void __launch_bounds__(128) prep_w_frag(
        const float* __restrict__ Wp, uint4* __restrict__ wfrag) {
    __shared__ __align__(16) __half Wsm[4][64 * 64];   // 32 KB
    const int t = threadIdx.x, wid = t >> 5, lane = t & 31;
    const int k = blockIdx.x * 4 + wid;
    __half* W = Wsm[wid];
#pragma unroll
    for (int i = 0; i < 16; i++) {
        int idx = i * 32 + lane;         // 0..511
        int d = idx >> 3, ch = idx & 7;
        const float4* gp = (const float4*)(Wp + (size_t)(d * 32 + k) * DIM + ch * 8);
        *(uint4*)(W + (d << 6) + ((ch ^ (d & 7)) << 3)) = f8_to_h8(gp[0], gp[1]);
    }
    __syncwarp();
#pragma unroll
    for (int ks = 0; ks < 4; ks++) {
        const int lrow = lane & 15;
        const int lch  = 2 * ks + (lane >> 4);
#pragma unroll
        for (int nb = 0; nb < 4; nb++) {
            int r = nb * 16 + lrow;
            uint32_t addr = smem_u32(W + r * 64 + (lch ^ (r & 7)) * 8);
            uint32_t b0, b1, b2, b3;
            asm volatile("ldmatrix.sync.aligned.m8n8.x4.shared.b16 {%0,%1,%2,%3}, [%4];"
                : "=r"(b0), "=r"(b1), "=r"(b2), "=r"(b3) : "r"(addr));
            wfrag[((k * 4 + ks) * 4 + nb) * 32 + lane] = make_uint4(b0, b1, b2, b3);
        }
    }
}
// K2b (side): permute b_p
__global__ void prep_bias(const float* __restrict__ bp, float* __restrict__ bperm) {
    int i = blockIdx.x * blockDim.x + threadIdx.x;   // 2048 threads
    int k = i >> 6, d = i & 63;
    bperm[i] = bp[d * 32 + k];
}

// ---------------------------------------------------------------------------
// K3: fused bilinear, smem-staged W. Per 64-channel tile (128 threads):
//   for k: P[v,d] = sum_j S[v,j]*W[(d,k),j] + cnt[v]*b_p[(d,k)]  (mma.m16n8k16)
//          m_in[v,k] = sum_d hin[v,d]*P[v,d]; m_out with hout.
// W fragments stream through a 2x32KB smem ring, 4 k per chunk (8 chunks),
// cp.async prefetch + 1 barrier per chunk. All 4 warps share each chunk ->
// wfrag L2 traffic drops 4x vs per-warp LDG (the round-11 bottleneck).
// Dynamic smem layout (bytes):
#define FB_W     0          // 2 x 32768 (double-buffered W chunks)
#define FB_S     65536      // 8192: S tile fp16 swizzled
#define FB_BP    73728      // 8192: bias perm f32
#define FB_MIN   81920      // 8448: [64][33] f32
#define FB_MOUT  90368      // 8448
#define FB_CNT   98816      // 256
#define FB_TOTAL 99072

__global__ void __launch_bounds__(128) fused_bilinear(
        const float* __restrict__ s, const float* __restrict__ cnt,
        const float* __restrict__ hin, const float* __restrict__ hout,
        const uint4* __restrict__ wfrag, const float* __restrict__ bperm,
        float* __restrict__ min_, float* __restrict__ mout_) {
    extern __shared__ __align__(16) char sm[];
    uint4*  Wbuf = (uint4*)(sm + FB_W);
    __half* Ssm  = (__half*)(sm + FB_S);
    float*  BPs  = (float*)(sm + FB_BP);
    float*  Min  = (float*)(sm + FB_MIN);
    float*  Mout = (float*)(sm + FB_MOUT);
    float*  CNTs = (float*)(sm + FB_CNT);

    const int t = threadIdx.x, wid = t >> 5, lane = t & 31;
    const int vt0 = blockIdx.x * VT;

    // prefetch W chunk 0 (k = 0..3): 32 KB, 2048 uint4, 16 per thread
#pragma unroll
    for (int i = 0; i < 16; i++) {
        int idx = i * 128 + t;
        uint32_t dsm = smem_u32(Wbuf + idx);
        asm volatile("cp.async.ca.shared.global [%0], [%1], 16;"
                     :: "r"(dsm), "l"(wfrag + idx));
    }
    asm volatile("cp.async.commit_group;");

#pragma unroll
    for (int i = 0; i < 4; i++) {
        int idx = i * 128 + t;           // 0..511
        int r = idx >> 3, ch = idx & 7;
        const float4* gp = (const float4*)(s + (size_t)(vt0 + r) * DIM + ch * 8);
        *(uint4*)(Ssm + r * 64 + ((ch ^ (r & 7)) << 3)) = f8_to_h8(gp[0], gp[1]);
    }
    for (int i = t; i < 512; i += 128)
        ((float4*)BPs)[i] = ((const float4*)bperm)[i];
    if (t < 64) CNTs[t] = cnt[vt0 + t];
    __syncthreads();

    const int vbase = wid * 16;
    uint32_t a[4][4];
    {
        const int r = vbase + (lane & 15);
#pragma unroll
        for (int ks = 0; ks < 4; ks++) {
            int lch = 2 * ks + (lane >> 4);
            uint32_t addr = smem_u32(Ssm + r * 64 + ((lch ^ (r & 7)) << 3));
            asm volatile("ldmatrix.sync.aligned.m8n8.x4.shared.b16 {%0,%1,%2,%3}, [%4];"
                : "=r"(a[ks][0]), "=r"(a[ks][1]), "=r"(a[ks][2]), "=r"(a[ks][3])
                : "r"(addr));
        }
    }
    const int tr0 = vbase + (lane >> 2);   // local row
    const int tr1 = tr0 + 8;
    const float cnt0 = CNTs[tr0];
    const float cnt1 = CNTs[tr1];
    const int dq = 2 * (lane & 3);

    // hoist h into registers (k-invariant)
    float2 hi0[8], hi1[8], ho0[8], ho1[8];
#pragma unroll
    for (int n8 = 0; n8 < 8; n8++) {
        int d0 = n8 * 8 + dq;
        hi0[n8] = *(const float2*)(hin  + (size_t)(vt0 + tr0) * DIM + d0);
        hi1[n8] = *(const float2*)(hin  + (size_t)(vt0 + tr1) * DIM + d0);
        ho0[n8] = *(const float2*)(hout + (size_t)(vt0 + tr0) * DIM + d0);
        ho1[n8] = *(const float2*)(hout + (size_t)(vt0 + tr1) * DIM + d0);
    }

    for (int chk = 0; chk < 8; chk++) {       // 4 k per chunk
        asm volatile("cp.async.wait_group 0;");
        __syncthreads();   // chunk ready AND all warps past previous chunk
        const uint4* Wc = Wbuf + (chk & 1) * 2048;
        if (chk < 7) {
            const uint4* gsrc = wfrag + (chk + 1) * 2048;
            uint4* dbuf = Wbuf + ((chk + 1) & 1) * 2048;
#pragma unroll
            for (int i = 0; i < 16; i++) {
                int idx = i * 128 + t;
                uint32_t dsm = smem_u32(dbuf + idx);
                asm volatile("cp.async.ca.shared.global [%0], [%1], 16;"
                             :: "r"(dsm), "l"(gsrc + idx));
            }
            asm volatile("cp.async.commit_group;");
        }

#pragma unroll
        for (int kk = 0; kk < 4; kk++) {
            const int k = chk * 4 + kk;
            float pacc[8][4];
#pragma unroll
            for (int n8 = 0; n8 < 8; n8++)
#pragma unroll
                for (int j = 0; j < 4; j++) pacc[n8][j] = 0.f;

            const uint4* wf = Wc + kk * 512 + lane;
#pragma unroll
            for (int ks = 0; ks < 4; ks++) {
                uint4 bf[4];
#pragma unroll
                for (int nb = 0; nb < 4; nb++) bf[nb] = wf[(ks * 4 + nb) * 32];
#pragma unroll
                for (int n8 = 0; n8 < 8; n8++) {
                    uint32_t b0 = (n8 & 1) ? bf[n8 >> 1].y : bf[n8 >> 1].x;
                    uint32_t b1 = (n8 & 1) ? bf[n8 >> 1].w : bf[n8 >> 1].z;
                    asm volatile(
                        "mma.sync.aligned.m16n8k16.row.col.f32.f16.f16.f32 "
                        "{%0,%1,%2,%3}, {%4,%5,%6,%7}, {%8,%9}, {%0,%1,%2,%3};"
                        : "+f"(pacc[n8][0]), "+f"(pacc[n8][1]),
                          "+f"(pacc[n8][2]), "+f"(pacc[n8][3])
                        : "r"(a[ks][0]), "r"(a[ks][1]), "r"(a[ks][2]), "r"(a[ks][3]),
                          "r"(b0), "r"(b1));
                }
            }

            float pin0 = 0.f, pin1 = 0.f, po0 = 0.f, po1 = 0.f;
            const float* bpk = BPs + k * 64;
#pragma unroll
            for (int n8 = 0; n8 < 8; n8++) {
                float2 bp2 = *(const float2*)(bpk + n8 * 8 + dq);
                float p00 = pacc[n8][0] + cnt0 * bp2.x;
                float p01 = pacc[n8][1] + cnt0 * bp2.y;
                float p10 = pacc[n8][2] + cnt1 * bp2.x;
                float p11 = pacc[n8][3] + cnt1 * bp2.y;
                pin0 += p00 * hi0[n8].x + p01 * hi0[n8].y;
                pin1 += p10 * hi1[n8].x + p11 * hi1[n8].y;
                po0  += p00 * ho0[n8].x + p01 * ho0[n8].y;
                po1  += p10 * ho1[n8].x + p11 * ho1[n8].y;
            }
            pin0 += __shfl_xor_sync(0xffffffffu, pin0, 1);
            pin0 += __shfl_xor_sync(0xffffffffu, pin0, 2);
            pin1 += __shfl_xor_sync(0xffffffffu, pin1, 1);
            pin1 += __shfl_xor_sync(0xffffffffu, pin1, 2);
            po0  += __shfl_xor_sync(0xffffffffu, po0, 1);
            po0  += __shfl_xor_sync(0xffffffffu, po0, 2);
            po1  += __shfl_xor_sync(0xffffffffu, po1, 1);
            po1  += __shfl_xor_sync(0xffffffffu, po1, 2);
            if ((lane & 3) == 0) {
                Min [tr0 * 33 + k] = pin0;
                Min [tr1 * 33 + k] = pin1;
                Mout[tr0 * 33 + k] = po0;
                Mout[tr1 * 33 + k] = po1;
            }
        }
    }
    __syncthreads();

    // dense writeback
    for (int i = t; i < 512; i += 128) {
        int r = i >> 3, c = (i & 7) * 4;
        float4 vi = make_float4(Min[r * 33 + c], Min[r * 33 + c + 1],
                                Min[r * 33 + c + 2], Min[r * 33 + c + 3]);
        float4 vo = make_float4(Mout[r * 33 + c], Mout[r * 33 + c + 1],
                                Mout[r * 33 + c + 2], Mout[r * 33 + c + 3]);
        *(float4*)(min_  + (size_t)(vt0 + r) * 32 + c) = vi;
        *(float4*)(mout_ + (size_t)(vt0 + r) * 32 + c) = vo;
    }
}

// ---------------------------------------------------------------------------
// K4: gather channel -> router into d_out. 8 lanes per edge, float4 chunks.
__global__ void gather_kernel(const int* __restrict__ isrc, const int* __restrict__ idst,
                              const int* __restrict__ oisrc, const int* __restrict__ oidst,
                              const float* __restrict__ min_, const float* __restrict__ mout_,
                              float* __restrict__ out) {
    int gtid = blockIdx.x * blockDim.x + threadIdx.x;
    int e = gtid >> 3;
    int c = gtid & 7;
    if (e < ERC) {
        int s = isrc[e], d = idst[e];
        float4 v = *(const float4*)(min_ + (size_t)s * 32 + c * 4);
        red_add_v4(out + (size_t)d * DIM + c * 4, v);
    } else if (e < 2 * ERC) {
        int ee = e - ERC;
        int s = oisrc[ee], d = oidst[ee];
        float4 v = *(const float4*)(mout_ + (size_t)s * 32 + c * 4);
        red_add_v4(out + (size_t)d * DIM + 32 + c * 4, v);
    }
}

// ---------------------------------------------------------------------------
// K5: relu epilogue on out
__global__ void relu_kernel(float4* __restrict__ out) {
    int i = blockIdx.x * blockDim.x + threadIdx.x;
    float4 v = out[i];
    v.x = fmaxf(v.x, 0.f); v.y = fmaxf(v.y, 0.f);
    v.z = fmaxf(v.z, 0.f); v.w = fmaxf(v.w, 0.f);
    out[i] = v;
}

// ===========================================================================
extern "C" void kernel_launch(void* const* d_in, const int* in_sizes, int n_in,
                              void* d_out, int out_size) {
    const float* h_router       = (const float*)d_in[0];
    const float* h_packet       = (const float*)d_in[1];
    const float* W_p            = (const float*)d_in[2];
    const float* b_p            = (const float*)d_in[3];
    // d_in[4] = W_c, d_in[5] = b_c : dead code in reference
    const int* output_src       = (const int*)d_in[6];
    const int* output_dst       = (const int*)d_in[7];
    const int* input_inv_src    = (const int*)d_in[8];
    const int* input_inv_dst    = (const int*)d_in[9];
    const int* pass_src         = (const int*)d_in[10];
    const int* pass_dst         = (const int*)d_in[11];
    const int* input_src        = (const int*)d_in[12];
    const int* input_dst        = (const int*)d_in[13];
    const int* output_inv_src   = (const int*)d_in[14];
    const int* output_inv_dst   = (const int*)d_in[15];
    float* out = (float*)d_out;

    float *p_s, *p_cnt, *p_hin, *p_hout, *p_min, *p_mout, *p_bperm;
    uint4* p_wfrag;
    cudaGetSymbolAddress((void**)&p_s,     g_s);
    cudaGetSymbolAddress((void**)&p_cnt,   g_cnt);
    cudaGetSymbolAddress((void**)&p_hin,   g_hin);
    cudaGetSymbolAddress((void**)&p_hout,  g_hout);
    cudaGetSymbolAddress((void**)&p_min,   g_min);
    cudaGetSymbolAddress((void**)&p_mout,  g_mout);
    cudaGetSymbolAddress((void**)&p_wfrag, g_wfrag);
    cudaGetSymbolAddress((void**)&p_bperm, g_bperm);

    cudaFuncSetAttribute(fused_bilinear,
                         cudaFuncAttributeMaxDynamicSharedMemorySize, FB_TOTAL);

    // Fork: side stream preps W fragments + bias permutation, zeroes out.
    cudaEventRecord(g_ss.evFork, 0);
    cudaStreamWaitEvent(g_ss.s2, g_ss.evFork, 0);
    prep_w_frag<<<8, 128, 0, g_ss.s2>>>(W_p, p_wfrag);
    prep_bias<<<8, 256, 0, g_ss.s2>>>(b_p, p_bperm);
    zero_out_kernel<<<(NR * DIM) / (4 * 256), 256, 0, g_ss.s2>>>((float4*)out);
    cudaEventRecord(g_ss.evJoin, g_ss.s2);

    // Main: zero accumulators, then all three scatters in one launch
    zero_hs_kernel<<<4096, 256>>>((float4*)p_hin, (float4*)p_hout,
                                  (float4*)p_s, (float4*)p_cnt);
    mega_scatter_kernel<<<(3 * ERC * 16) / 256, 256>>>(
        output_src, output_dst, input_inv_src, input_inv_dst,
        pass_src, pass_dst, h_router, h_packet,
        p_hin, p_hout, p_s, p_cnt);

    // Join, then fused bilinear (needs scatters + prep)
    cudaStreamWaitEvent(0, g_ss.evJoin, 0);
    fused_bilinear<<<NCH / VT, 128, FB_TOTAL>>>(p_s, p_cnt, p_hin, p_hout,
                                                p_wfrag, p_bperm, p_min, p_mout);

    // channel -> router gathers into out
    gather_kernel<<<(2 * ERC * 8) / 256, 256>>>(input_src, input_dst,
                                                output_inv_src, output_inv_dst,
                                                p_min, p_mout, out);

    // relu epilogue
    relu_kernel<<<(NR * DIM) / (4 * 256), 256>>>((float4*)out);
}